// round 5
// baseline (speedup 1.0000x reference)
#include <cuda_runtime.h>
#include <cstdint>

// ---------------------------------------------------------------------------
// HeteroGraphConv, D=128 fixed.
//
// Pipeline (all edge aggregation via CSR gather, no payload atomics):
//   preprocess dir: hist(dst) -> exclusive scan -> fill perm (src, ea)
//   H = relu(x_src @ w1 + b1)            (gemm mode0)
//   T = H @ w2 + b2                      (gemm mode1)
//   aggr_dst[d] = x_dst[d] + sum_e w_e * T[src_e]   (gather kernel, warp/row)
//   out = relu(LN(aggr @ wu + bu)*g + be)           (gemm mode2, in-place on out)
// ---------------------------------------------------------------------------

#define D128 128
#define BM 64
#define BK 8
#define MAXN 50176   // capacity rows (>= 50000)
#define MAXE 450048  // capacity edges (>= 400000)

// Scratch (allocation-free rule: __device__ globals)
__device__ float g_H[MAXN * D128];
__device__ float g_T[MAXN * D128];
__device__ int   g_cnt [2][MAXN];      // histogram, then reused as fill cursor
__device__ int   g_off [2][MAXN + 1];  // CSR row offsets
__device__ int   g_psrc[2][MAXE];      // permuted src indices
__device__ float g_pw  [2][MAXE];      // permuted edge weights

// ---------------------------------------------------------------------------
// GEMM  C[M,128] = A[M,128] @ W[128,128] (+ epilogue)
// MODE: 0 = bias+relu, 1 = bias, 2 = bias + LayerNorm(g,be) + relu
// MODE 2 is safe in-place (C == A): each block reads only its own rows.
// ---------------------------------------------------------------------------
template <int MODE>
__global__ __launch_bounds__(256, 4)
void gemm128_kernel(const float* __restrict__ A,
                    const float* __restrict__ W,   // [128,128] row-major (k,n)
                    const float* __restrict__ bias,
                    const float* __restrict__ gamma,
                    const float* __restrict__ beta,
                    float* __restrict__ C,
                    int M)
{
    __shared__ float As[BK][BM];     // A^T tile: As[k][m]
    __shared__ float Ws[BK][D128];   // W tile:   Ws[k][n]

    const int tid = threadIdx.x;
    const int tx  = tid & 31;        // lane: owns cols tx*4 .. tx*4+3
    const int ty  = tid >> 5;        // warp: owns rows ty*8 .. ty*8+7
    const int row0 = blockIdx.x * BM;

    float acc[8][4];
    #pragma unroll
    for (int i = 0; i < 8; i++)
        #pragma unroll
        for (int j = 0; j < 4; j++) acc[i][j] = 0.0f;

    for (int k0 = 0; k0 < D128; k0 += BK) {
        if (tid < 128) {
            int r  = tid >> 1;
            int c4 = (tid & 1) * 4;
            int grow = row0 + r;
            float4 v = make_float4(0.f, 0.f, 0.f, 0.f);
            if (grow < M)
                v = *reinterpret_cast<const float4*>(A + (size_t)grow * D128 + k0 + c4);
            As[c4 + 0][r] = v.x;
            As[c4 + 1][r] = v.y;
            As[c4 + 2][r] = v.z;
            As[c4 + 3][r] = v.w;
        }
        {
            int r  = tid >> 5;
            int c4 = (tid & 31) * 4;
            *reinterpret_cast<float4*>(&Ws[r][c4]) =
                *reinterpret_cast<const float4*>(W + (size_t)(k0 + r) * D128 + c4);
        }
        __syncthreads();

        #pragma unroll
        for (int kk = 0; kk < BK; kk++) {
            float4 a0 = *reinterpret_cast<const float4*>(&As[kk][ty * 8]);
            float4 a1 = *reinterpret_cast<const float4*>(&As[kk][ty * 8 + 4]);
            float4 w  = *reinterpret_cast<const float4*>(&Ws[kk][tx * 4]);
            float av[8] = {a0.x, a0.y, a0.z, a0.w, a1.x, a1.y, a1.z, a1.w};
            #pragma unroll
            for (int i = 0; i < 8; i++) {
                acc[i][0] = fmaf(av[i], w.x, acc[i][0]);
                acc[i][1] = fmaf(av[i], w.y, acc[i][1]);
                acc[i][2] = fmaf(av[i], w.z, acc[i][2]);
                acc[i][3] = fmaf(av[i], w.w, acc[i][3]);
            }
        }
        __syncthreads();
    }

    float4 bv = *reinterpret_cast<const float4*>(bias + tx * 4);

    if (MODE == 0) {
        #pragma unroll
        for (int i = 0; i < 8; i++) {
            int grow = row0 + ty * 8 + i;
            if (grow < M) {
                float4 o;
                o.x = fmaxf(acc[i][0] + bv.x, 0.f);
                o.y = fmaxf(acc[i][1] + bv.y, 0.f);
                o.z = fmaxf(acc[i][2] + bv.z, 0.f);
                o.w = fmaxf(acc[i][3] + bv.w, 0.f);
                *reinterpret_cast<float4*>(C + (size_t)grow * D128 + tx * 4) = o;
            }
        }
    } else if (MODE == 1) {
        #pragma unroll
        for (int i = 0; i < 8; i++) {
            int grow = row0 + ty * 8 + i;
            if (grow < M) {
                float4 o;
                o.x = acc[i][0] + bv.x;
                o.y = acc[i][1] + bv.y;
                o.z = acc[i][2] + bv.z;
                o.w = acc[i][3] + bv.w;
                *reinterpret_cast<float4*>(C + (size_t)grow * D128 + tx * 4) = o;
            }
        }
    } else {  // bias + LayerNorm + relu; each warp owns full 128-col rows
        float4 gv = *reinterpret_cast<const float4*>(gamma + tx * 4);
        float4 ev = *reinterpret_cast<const float4*>(beta  + tx * 4);
        #pragma unroll
        for (int i = 0; i < 8; i++) {
            float h0 = acc[i][0] + bv.x;
            float h1 = acc[i][1] + bv.y;
            float h2 = acc[i][2] + bv.z;
            float h3 = acc[i][3] + bv.w;
            float s = h0 + h1 + h2 + h3;
            #pragma unroll
            for (int off = 16; off > 0; off >>= 1)
                s += __shfl_xor_sync(0xFFFFFFFFu, s, off);
            float mu = s * (1.0f / 128.0f);
            float d0 = h0 - mu, d1 = h1 - mu, d2 = h2 - mu, d3 = h3 - mu;
            float q = d0 * d0 + d1 * d1 + d2 * d2 + d3 * d3;
            #pragma unroll
            for (int off = 16; off > 0; off >>= 1)
                q += __shfl_xor_sync(0xFFFFFFFFu, q, off);
            float rstd = rsqrtf(q * (1.0f / 128.0f) + 1e-5f);
            int grow = row0 + ty * 8 + i;
            if (grow < M) {
                float4 o;
                o.x = fmaxf(d0 * rstd * gv.x + ev.x, 0.f);
                o.y = fmaxf(d1 * rstd * gv.y + ev.y, 0.f);
                o.z = fmaxf(d2 * rstd * gv.z + ev.z, 0.f);
                o.w = fmaxf(d3 * rstd * gv.w + ev.w, 0.f);
                *reinterpret_cast<float4*>(C + (size_t)grow * D128 + tx * 4) = o;
            }
        }
    }
}

// ---------------------------------------------------------------------------
// CSR construction: histogram -> exclusive scan -> cursor fill
// ---------------------------------------------------------------------------
__global__ void hist_kernel(const int* __restrict__ dst, int E, int* __restrict__ cnt)
{
    int e = blockIdx.x * blockDim.x + threadIdx.x;
    if (e < E) atomicAdd(&cnt[dst[e]], 1);
}

// Single-block exclusive scan over n (<= ~64k) elements; writes off[0..n].
__global__ __launch_bounds__(1024)
void scan_kernel(const int* __restrict__ cnt, int* __restrict__ off, int n)
{
    __shared__ int wsum[32];
    __shared__ int s_running;
    const int tid = threadIdx.x, lane = tid & 31, wid = tid >> 5;
    if (tid == 0) s_running = 0;
    __syncthreads();

    for (int base = 0; base < n; base += 1024) {
        int i = base + tid;
        int v = (i < n) ? cnt[i] : 0;
        int x = v;
        #pragma unroll
        for (int o = 1; o < 32; o <<= 1) {
            int y = __shfl_up_sync(0xFFFFFFFFu, x, o);
            if (lane >= o) x += y;
        }
        if (lane == 31) wsum[wid] = x;
        __syncthreads();
        if (wid == 0) {
            int w = wsum[lane];
            #pragma unroll
            for (int o = 1; o < 32; o <<= 1) {
                int y = __shfl_up_sync(0xFFFFFFFFu, w, o);
                if (lane >= o) w += y;
            }
            wsum[lane] = w;
        }
        __syncthreads();
        int warp_excl = (wid == 0) ? 0 : wsum[wid - 1];
        int run = s_running;                 // read before update
        if (i < n) off[i] = run + warp_excl + x - v;
        int total = wsum[31];
        __syncthreads();
        if (tid == 0) s_running = run + total;
        __syncthreads();
    }
    if (tid == 0) off[n] = s_running;
}

__global__ void fill_kernel(const int* __restrict__ src, const int* __restrict__ dst,
                            const float* __restrict__ ea, int E,
                            const int* __restrict__ off, int* __restrict__ cur,
                            int* __restrict__ psrc, float* __restrict__ pw)
{
    int e = blockIdx.x * blockDim.x + threadIdx.x;
    if (e >= E) return;
    int d = dst[e];
    int pos = off[d] + atomicAdd(&cur[d], 1);
    psrc[pos] = src[e];
    pw[pos]   = ea[e];
}

// ---------------------------------------------------------------------------
// Gather aggregation: one warp per dst row.
// aggr[d] = x[d] + sum_{j in [off[d],off[d+1])} pw[j] * T[psrc[j]]
// ---------------------------------------------------------------------------
__global__ __launch_bounds__(256)
void gather_kernel(const float* __restrict__ T,
                   const float* __restrict__ x,
                   const int* __restrict__ off,
                   const int* __restrict__ psrc,
                   const float* __restrict__ pw,
                   float* __restrict__ aggr,
                   int N)
{
    int w    = (blockIdx.x * blockDim.x + threadIdx.x) >> 5;
    int lane = threadIdx.x & 31;
    if (w >= N) return;

    float4 acc = reinterpret_cast<const float4*>(x + (size_t)w * D128)[lane];

    int j  = off[w];
    int s1 = off[w + 1];

    for (; j + 1 < s1; j += 2) {
        int   sA = psrc[j],   sB = psrc[j + 1];
        float wA = pw[j],     wB = pw[j + 1];
        float4 vA = reinterpret_cast<const float4*>(T + (size_t)sA * D128)[lane];
        float4 vB = reinterpret_cast<const float4*>(T + (size_t)sB * D128)[lane];
        acc.x = fmaf(wA, vA.x, acc.x); acc.x = fmaf(wB, vB.x, acc.x);
        acc.y = fmaf(wA, vA.y, acc.y); acc.y = fmaf(wB, vB.y, acc.y);
        acc.z = fmaf(wA, vA.z, acc.z); acc.z = fmaf(wB, vB.z, acc.z);
        acc.w = fmaf(wA, vA.w, acc.w); acc.w = fmaf(wB, vB.w, acc.w);
    }
    if (j < s1) {
        int   sA = psrc[j];
        float wA = pw[j];
        float4 vA = reinterpret_cast<const float4*>(T + (size_t)sA * D128)[lane];
        acc.x = fmaf(wA, vA.x, acc.x);
        acc.y = fmaf(wA, vA.y, acc.y);
        acc.z = fmaf(wA, vA.z, acc.z);
        acc.w = fmaf(wA, vA.w, acc.w);
    }

    reinterpret_cast<float4*>(aggr + (size_t)w * D128)[lane] = acc;
}

extern "C" void kernel_launch(void* const* d_in, const int* in_sizes, int n_in,
                              void* d_out, int out_size)
{
    const float* x_a   = (const float*)d_in[0];
    const float* x_b   = (const float*)d_in[1];
    const int*   ei_ab = (const int*)  d_in[2];   // [2,E]
    const float* ea_ab = (const float*)d_in[3];
    const int*   ei_ba = (const int*)  d_in[4];
    const float* ea_ba = (const float*)d_in[5];
    const float* w1_ab = (const float*)d_in[6];
    const float* b1_ab = (const float*)d_in[7];
    const float* w2_ab = (const float*)d_in[8];
    const float* b2_ab = (const float*)d_in[9];
    const float* w1_ba = (const float*)d_in[10];
    const float* b1_ba = (const float*)d_in[11];
    const float* w2_ba = (const float*)d_in[12];
    const float* b2_ba = (const float*)d_in[13];
    const float* wu_a  = (const float*)d_in[14];
    const float* bu_a  = (const float*)d_in[15];
    const float* g_a   = (const float*)d_in[16];
    const float* be_a  = (const float*)d_in[17];
    const float* wu_b  = (const float*)d_in[18];
    const float* bu_b  = (const float*)d_in[19];
    const float* g_b   = (const float*)d_in[20];
    const float* be_b  = (const float*)d_in[21];

    const int NA   = in_sizes[0] / D128;
    const int NB   = in_sizes[1] / D128;
    const int E_ab = in_sizes[3];
    const int E_ba = in_sizes[5];

    float* H = nullptr; float* T = nullptr;
    int *cnt0, *cnt1, *off0, *off1, *ps0, *ps1;
    float *pw0, *pw1;
    cudaGetSymbolAddress((void**)&H, g_H);
    cudaGetSymbolAddress((void**)&T, g_T);
    { void* p; cudaGetSymbolAddress(&p, g_cnt);  cnt0 = (int*)p;  cnt1 = cnt0 + MAXN; }
    { void* p; cudaGetSymbolAddress(&p, g_off);  off0 = (int*)p;  off1 = off0 + (MAXN + 1); }
    { void* p; cudaGetSymbolAddress(&p, g_psrc); ps0  = (int*)p;  ps1  = ps0 + MAXE; }
    { void* p; cudaGetSymbolAddress(&p, g_pw);   pw0  = (float*)p; pw1 = pw0 + MAXE; }

    float* out    = (float*)d_out;
    float* aggr_a = out;                       // in-place region for out_a
    float* aggr_b = out + (size_t)NA * D128;   // in-place region for out_b

    const int blkA = (NA + BM - 1) / BM;
    const int blkB = (NB + BM - 1) / BM;
    const int eblkA = (E_ab + 255) / 256;
    const int eblkB = (E_ba + 255) / 256;

    // --- CSR preprocessing, both directions ---
    // dir 0: a->b (dst in b, count NB); dir 1: b->a (dst in a, count NA)
    cudaMemsetAsync(cnt0, 0, sizeof(int) * MAXN * 2, 0);
    hist_kernel<<<eblkA, 256>>>(ei_ab + E_ab, E_ab, cnt0);
    hist_kernel<<<eblkB, 256>>>(ei_ba + E_ba, E_ba, cnt1);
    scan_kernel<<<1, 1024>>>(cnt0, off0, NB);
    scan_kernel<<<1, 1024>>>(cnt1, off1, NA);
    cudaMemsetAsync(cnt0, 0, sizeof(int) * MAXN * 2, 0);   // reuse as cursors
    fill_kernel<<<eblkA, 256>>>(ei_ab, ei_ab + E_ab, ea_ab, E_ab, off0, cnt0, ps0, pw0);
    fill_kernel<<<eblkB, 256>>>(ei_ba, ei_ba + E_ba, ea_ba, E_ba, off1, cnt1, ps1, pw1);

    // --- a -> b: edge MLP on x_a, gather into aggr_b (residual folded in) ---
    gemm128_kernel<0><<<blkA, 256>>>(x_a, w1_ab, b1_ab, nullptr, nullptr, H, NA);
    gemm128_kernel<1><<<blkA, 256>>>(H,   w2_ab, b2_ab, nullptr, nullptr, T, NA);
    gather_kernel<<<(NB + 7) / 8, 256>>>(T, x_b, off0, ps0, pw0, aggr_b, NB);

    // --- b -> a ---
    gemm128_kernel<0><<<blkB, 256>>>(x_b, w1_ba, b1_ba, nullptr, nullptr, H, NB);
    gemm128_kernel<1><<<blkB, 256>>>(H,   w2_ba, b2_ba, nullptr, nullptr, T, NB);
    gather_kernel<<<(NA + 7) / 8, 256>>>(T, x_a, off1, ps1, pw1, aggr_a, NA);

    // --- node updates: fused GEMM + LayerNorm + ReLU, in place on out ---
    gemm128_kernel<2><<<blkA, 256>>>(aggr_a, wu_a, bu_a, g_a, be_a, aggr_a, NA);
    gemm128_kernel<2><<<blkB, 256>>>(aggr_b, wu_b, bu_b, g_b, be_b, aggr_b, NB);
}

// round 6
// speedup vs baseline: 1.8850x; 1.8850x over previous
#include <cuda_runtime.h>
#include <cstdint>

// ---------------------------------------------------------------------------
// HeteroGraphConv, D=128.
//   CSR preprocess: hist -> 3-stage scan -> fill
//   per direction: T = (relu(x@w1+b1))@w2+b2   (2x tf32 mma.sync GEMMs)
//                  aggr[d] = x[d] + sum w_e*T[src_e]  (CSR gather, warp/row)
//   out = relu(LN(aggr@wu+bu)*g+be)            (tf32 GEMM + fused LN, in-place)
// ---------------------------------------------------------------------------

#define D128 128
#define MAXN 50176
#define MAXE 450048

__device__ float g_H[MAXN * D128];
__device__ float g_T[MAXN * D128];
__device__ int   g_cnt [2][MAXN];
__device__ int   g_off [2][MAXN + 1];
__device__ int   g_bsum[2][64];
__device__ int   g_psrc[2][MAXE];
__device__ float g_pw  [2][MAXE];

// ---------------------------------------------------------------------------
// tf32 tensor-core GEMM: C[M,128] = A[M,128] @ W[128,128] + epilogue
// MODE: 0 = bias+relu, 1 = bias, 2 = bias+LayerNorm+relu (in-place safe)
// ---------------------------------------------------------------------------
#define BM 128
#define BKC 32
#define AS_STRIDE 36                 // 32 + 4 pad: conflict-free frag loads
#define WS_STRIDE 132                // 128 + 4 pad
#define AS_SIZE (BM * AS_STRIDE)     // 4608 floats
#define WS_SIZE (BKC * WS_STRIDE)   // 4224 floats
#define BUF_SIZE (AS_SIZE + WS_SIZE)
#define SMEM_FLOATS (2 * BUF_SIZE)   // 17664 floats = 70656 B (>= 128*132 LN tile)

__device__ __forceinline__ unsigned f2tf32(float f) {
    unsigned r;
    asm("cvt.rna.tf32.f32 %0, %1;" : "=r"(r) : "f"(f));
    return r;
}

template <int MODE>
__global__ __launch_bounds__(256)
void gemm_tc(const float* __restrict__ A,
             const float* __restrict__ W,     // [k][n] row-major
             const float* __restrict__ bias,
             const float* __restrict__ gamma,
             const float* __restrict__ beta,
             float* __restrict__ C,
             int M)
{
    extern __shared__ float smem[];

    const int tid  = threadIdx.x;
    const int lane = tid & 31;
    const int wid  = tid >> 5;
    const int wm   = wid >> 1;          // 0..3 : rows wm*32
    const int wn   = wid & 1;           // 0..1 : cols wn*64
    const int g    = lane >> 2;         // 0..7
    const int t    = lane & 3;          // 0..3
    const int row0 = blockIdx.x * BM;

    float acc[2][8][4];
    #pragma unroll
    for (int mf = 0; mf < 2; mf++)
        #pragma unroll
        for (int nf = 0; nf < 8; nf++)
            #pragma unroll
            for (int j = 0; j < 4; j++) acc[mf][nf][j] = 0.0f;

    float4 aLd[4], wLd[4];

    // --- load chunk kc (global) into regs ---
    auto ldg_chunk = [&](int kc) {
        #pragma unroll
        for (int i = 0; i < 4; i++) {
            int idx = tid + i * 256;          // 0..1023 float4s of A chunk
            int r = idx >> 3, c = (idx & 7) * 4;
            int gr = row0 + r;
            aLd[i] = (gr < M)
                ? *reinterpret_cast<const float4*>(A + (size_t)gr * D128 + kc + c)
                : make_float4(0.f, 0.f, 0.f, 0.f);
        }
        #pragma unroll
        for (int i = 0; i < 4; i++) {
            int idx = tid + i * 256;          // W chunk: 32 rows x 128
            int r = idx >> 5, c = (idx & 31) * 4;
            wLd[i] = *reinterpret_cast<const float4*>(W + (size_t)(kc + r) * D128 + c);
        }
    };
    // --- store regs (converted to tf32 bits) into smem buffer b ---
    auto sts_chunk = [&](int b) {
        float* as = smem + b * BUF_SIZE;
        float* ws = as + AS_SIZE;
        #pragma unroll
        for (int i = 0; i < 4; i++) {
            int idx = tid + i * 256;
            int r = idx >> 3, c = (idx & 7) * 4;
            float* p = as + r * AS_STRIDE + c;
            float4 o;
            o.x = __uint_as_float(f2tf32(aLd[i].x));
            o.y = __uint_as_float(f2tf32(aLd[i].y));
            o.z = __uint_as_float(f2tf32(aLd[i].z));
            o.w = __uint_as_float(f2tf32(aLd[i].w));
            *reinterpret_cast<float4*>(p) = o;
        }
        #pragma unroll
        for (int i = 0; i < 4; i++) {
            int idx = tid + i * 256;
            int r = idx >> 5, c = (idx & 31) * 4;
            float* p = ws + r * WS_STRIDE + c;
            float4 o;
            o.x = __uint_as_float(f2tf32(wLd[i].x));
            o.y = __uint_as_float(f2tf32(wLd[i].y));
            o.z = __uint_as_float(f2tf32(wLd[i].z));
            o.w = __uint_as_float(f2tf32(wLd[i].w));
            *reinterpret_cast<float4*>(p) = o;
        }
    };

    ldg_chunk(0);
    sts_chunk(0);
    __syncthreads();

    #pragma unroll
    for (int c = 0; c < 4; c++) {
        if (c < 3) ldg_chunk((c + 1) * BKC);

        const float* as = smem + (c & 1) * BUF_SIZE;
        const float* ws = as + AS_SIZE;

        #pragma unroll
        for (int ks = 0; ks < 4; ks++) {
            const int k0 = ks * 8;
            unsigned a[2][4];
            #pragma unroll
            for (int mf = 0; mf < 2; mf++) {
                const float* ap = as + (wm * 32 + mf * 16 + g) * AS_STRIDE + k0 + t;
                a[mf][0] = __float_as_uint(ap[0]);
                a[mf][1] = __float_as_uint(ap[8 * AS_STRIDE]);
                a[mf][2] = __float_as_uint(ap[4]);
                a[mf][3] = __float_as_uint(ap[8 * AS_STRIDE + 4]);
            }
            unsigned b[8][2];
            #pragma unroll
            for (int nf = 0; nf < 8; nf++) {
                const float* wp = ws + (k0 + t) * WS_STRIDE + wn * 64 + nf * 8 + g;
                b[nf][0] = __float_as_uint(wp[0]);
                b[nf][1] = __float_as_uint(wp[4 * WS_STRIDE]);
            }
            #pragma unroll
            for (int mf = 0; mf < 2; mf++)
                #pragma unroll
                for (int nf = 0; nf < 8; nf++)
                    asm volatile(
                        "mma.sync.aligned.m16n8k8.row.col.f32.tf32.tf32.f32 "
                        "{%0,%1,%2,%3}, {%4,%5,%6,%7}, {%8,%9}, {%0,%1,%2,%3};"
                        : "+f"(acc[mf][nf][0]), "+f"(acc[mf][nf][1]),
                          "+f"(acc[mf][nf][2]), "+f"(acc[mf][nf][3])
                        : "r"(a[mf][0]), "r"(a[mf][1]), "r"(a[mf][2]), "r"(a[mf][3]),
                          "r"(b[nf][0]), "r"(b[nf][1]));
        }
        __syncthreads();
        if (c < 3) {
            sts_chunk((c + 1) & 1);
            __syncthreads();
        }
    }

    if (MODE < 2) {
        #pragma unroll
        for (int mf = 0; mf < 2; mf++) {
            int r_ = row0 + wm * 32 + mf * 16 + g;
            #pragma unroll
            for (int nf = 0; nf < 8; nf++) {
                int col = wn * 64 + nf * 8 + 2 * t;
                float b0 = bias[col], b1 = bias[col + 1];
                float2 v0, v1;
                v0.x = acc[mf][nf][0] + b0; v0.y = acc[mf][nf][1] + b1;
                v1.x = acc[mf][nf][2] + b0; v1.y = acc[mf][nf][3] + b1;
                if (MODE == 0) {
                    v0.x = fmaxf(v0.x, 0.f); v0.y = fmaxf(v0.y, 0.f);
                    v1.x = fmaxf(v1.x, 0.f); v1.y = fmaxf(v1.y, 0.f);
                }
                if (r_ < M)
                    *reinterpret_cast<float2*>(C + (size_t)r_ * D128 + col) = v0;
                if (r_ + 8 < M)
                    *reinterpret_cast<float2*>(C + (size_t)(r_ + 8) * D128 + col) = v1;
            }
        }
    } else {
        // LayerNorm epilogue: frags -> smem tile -> warp-per-row reduce
        __syncthreads();
        float* S = smem;   // [128][132]
        #pragma unroll
        for (int mf = 0; mf < 2; mf++) {
            int r_ = wm * 32 + mf * 16 + g;
            #pragma unroll
            for (int nf = 0; nf < 8; nf++) {
                int col = wn * 64 + nf * 8 + 2 * t;
                S[r_ * 132 + col]           = acc[mf][nf][0];
                S[r_ * 132 + col + 1]       = acc[mf][nf][1];
                S[(r_ + 8) * 132 + col]     = acc[mf][nf][2];
                S[(r_ + 8) * 132 + col + 1] = acc[mf][nf][3];
            }
        }
        __syncthreads();

        float4 bv = *reinterpret_cast<const float4*>(bias  + lane * 4);
        float4 gv = *reinterpret_cast<const float4*>(gamma + lane * 4);
        float4 ev = *reinterpret_cast<const float4*>(beta  + lane * 4);

        #pragma unroll
        for (int rr = 0; rr < 16; rr++) {
            int r_ = wid * 16 + rr;
            float4 h = *reinterpret_cast<const float4*>(S + r_ * 132 + lane * 4);
            h.x += bv.x; h.y += bv.y; h.z += bv.z; h.w += bv.w;
            float s = h.x + h.y + h.z + h.w;
            #pragma unroll
            for (int o = 16; o > 0; o >>= 1)
                s += __shfl_xor_sync(0xFFFFFFFFu, s, o);
            float mu = s * (1.0f / 128.0f);
            float d0 = h.x - mu, d1 = h.y - mu, d2 = h.z - mu, d3 = h.w - mu;
            float q = d0 * d0 + d1 * d1 + d2 * d2 + d3 * d3;
            #pragma unroll
            for (int o = 16; o > 0; o >>= 1)
                q += __shfl_xor_sync(0xFFFFFFFFu, q, o);
            float rstd = rsqrtf(q * (1.0f / 128.0f) + 1e-5f);
            int grow = row0 + r_;
            if (grow < M) {
                float4 o4;
                o4.x = fmaxf(d0 * rstd * gv.x + ev.x, 0.f);
                o4.y = fmaxf(d1 * rstd * gv.y + ev.y, 0.f);
                o4.z = fmaxf(d2 * rstd * gv.z + ev.z, 0.f);
                o4.w = fmaxf(d3 * rstd * gv.w + ev.w, 0.f);
                *reinterpret_cast<float4*>(C + (size_t)grow * D128 + lane * 4) = o4;
            }
        }
    }
}

// ---------------------------------------------------------------------------
// CSR construction
// ---------------------------------------------------------------------------
__global__ void hist_kernel(const int* __restrict__ dst, int E, int* __restrict__ cnt)
{
    int e = blockIdx.x * blockDim.x + threadIdx.x;
    if (e < E) atomicAdd(&cnt[dst[e]], 1);
}

// Stage 1: per-block (1024-wide) exclusive scan; block totals to bsum.
__global__ __launch_bounds__(1024)
void scan1_kernel(const int* __restrict__ cnt, int* __restrict__ off,
                  int* __restrict__ bsum, int n)
{
    __shared__ int ws[32];
    const int tid = threadIdx.x, lane = tid & 31, wid = tid >> 5;
    int i = blockIdx.x * 1024 + tid;
    int v = (i < n) ? cnt[i] : 0;
    int x = v;
    #pragma unroll
    for (int o = 1; o < 32; o <<= 1) {
        int y = __shfl_up_sync(0xFFFFFFFFu, x, o);
        if (lane >= o) x += y;
    }
    if (lane == 31) ws[wid] = x;
    __syncthreads();
    if (wid == 0) {
        int w = ws[lane];
        #pragma unroll
        for (int o = 1; o < 32; o <<= 1) {
            int y = __shfl_up_sync(0xFFFFFFFFu, w, o);
            if (lane >= o) w += y;
        }
        ws[lane] = w;
    }
    __syncthreads();
    int excl = ((wid == 0) ? 0 : ws[wid - 1]) + x - v;
    if (i < n) off[i] = excl;
    if (tid == 0) bsum[blockIdx.x] = ws[31];
}

// Stage 2: exclusive scan of <=64 block sums (single block, 64 threads).
__global__ void scan2_kernel(int* __restrict__ bsum, int nb)
{
    __shared__ int s[64];
    int l = threadIdx.x;
    s[l] = (l < nb) ? bsum[l] : 0;
    __syncthreads();
    #pragma unroll
    for (int o = 1; o < 64; o <<= 1) {
        int t = (l >= o) ? s[l - o] : 0;
        __syncthreads();
        s[l] += t;
        __syncthreads();
    }
    if (l < nb) bsum[l] = (l > 0) ? s[l - 1] : 0;
}

// Stage 3: add block offsets; write off[n] = E.
__global__ void scan3_kernel(int* __restrict__ off, const int* __restrict__ bsum,
                             int n, int E)
{
    int i = blockIdx.x * blockDim.x + threadIdx.x;
    if (i < n) off[i] += bsum[i >> 10];
    if (i == 0) off[n] = E;
}

__global__ void fill_kernel(const int* __restrict__ src, const int* __restrict__ dst,
                            const float* __restrict__ ea, int E,
                            const int* __restrict__ off, int* __restrict__ cur,
                            int* __restrict__ psrc, float* __restrict__ pw)
{
    int e = blockIdx.x * blockDim.x + threadIdx.x;
    if (e >= E) return;
    int d = dst[e];
    int pos = off[d] + atomicAdd(&cur[d], 1);
    psrc[pos] = src[e];
    pw[pos]   = ea[e];
}

// ---------------------------------------------------------------------------
// Gather: one warp per dst row; residual folded in via init from x.
// ---------------------------------------------------------------------------
__global__ __launch_bounds__(256)
void gather_kernel(const float* __restrict__ T,
                   const float* __restrict__ x,
                   const int* __restrict__ off,
                   const int* __restrict__ psrc,
                   const float* __restrict__ pw,
                   float* __restrict__ aggr,
                   int N)
{
    int w    = (blockIdx.x * blockDim.x + threadIdx.x) >> 5;
    int lane = threadIdx.x & 31;
    if (w >= N) return;

    float4 acc = reinterpret_cast<const float4*>(x + (size_t)w * D128)[lane];

    int j  = off[w];
    int s1 = off[w + 1];

    for (; j + 1 < s1; j += 2) {
        int   sA = psrc[j],   sB = psrc[j + 1];
        float wA = pw[j],     wB = pw[j + 1];
        float4 vA = reinterpret_cast<const float4*>(T + (size_t)sA * D128)[lane];
        float4 vB = reinterpret_cast<const float4*>(T + (size_t)sB * D128)[lane];
        acc.x = fmaf(wA, vA.x, acc.x); acc.x = fmaf(wB, vB.x, acc.x);
        acc.y = fmaf(wA, vA.y, acc.y); acc.y = fmaf(wB, vB.y, acc.y);
        acc.z = fmaf(wA, vA.z, acc.z); acc.z = fmaf(wB, vB.z, acc.z);
        acc.w = fmaf(wA, vA.w, acc.w); acc.w = fmaf(wB, vB.w, acc.w);
    }
    if (j < s1) {
        int   sA = psrc[j];
        float wA = pw[j];
        float4 vA = reinterpret_cast<const float4*>(T + (size_t)sA * D128)[lane];
        acc.x = fmaf(wA, vA.x, acc.x);
        acc.y = fmaf(wA, vA.y, acc.y);
        acc.z = fmaf(wA, vA.z, acc.z);
        acc.w = fmaf(wA, vA.w, acc.w);
    }

    reinterpret_cast<float4*>(aggr + (size_t)w * D128)[lane] = acc;
}

extern "C" void kernel_launch(void* const* d_in, const int* in_sizes, int n_in,
                              void* d_out, int out_size)
{
    const float* x_a   = (const float*)d_in[0];
    const float* x_b   = (const float*)d_in[1];
    const int*   ei_ab = (const int*)  d_in[2];
    const float* ea_ab = (const float*)d_in[3];
    const int*   ei_ba = (const int*)  d_in[4];
    const float* ea_ba = (const float*)d_in[5];
    const float* w1_ab = (const float*)d_in[6];
    const float* b1_ab = (const float*)d_in[7];
    const float* w2_ab = (const float*)d_in[8];
    const float* b2_ab = (const float*)d_in[9];
    const float* w1_ba = (const float*)d_in[10];
    const float* b1_ba = (const float*)d_in[11];
    const float* w2_ba = (const float*)d_in[12];
    const float* b2_ba = (const float*)d_in[13];
    const float* wu_a  = (const float*)d_in[14];
    const float* bu_a  = (const float*)d_in[15];
    const float* g_a   = (const float*)d_in[16];
    const float* be_a  = (const float*)d_in[17];
    const float* wu_b  = (const float*)d_in[18];
    const float* bu_b  = (const float*)d_in[19];
    const float* g_b   = (const float*)d_in[20];
    const float* be_b  = (const float*)d_in[21];

    const int NA   = in_sizes[0] / D128;
    const int NB   = in_sizes[1] / D128;
    const int E_ab = in_sizes[3];
    const int E_ba = in_sizes[5];

    float* H = nullptr; float* T = nullptr;
    int *cnt0, *cnt1, *off0, *off1, *ps0, *ps1, *bs0, *bs1;
    float *pw0, *pw1;
    cudaGetSymbolAddress((void**)&H, g_H);
    cudaGetSymbolAddress((void**)&T, g_T);
    { void* p; cudaGetSymbolAddress(&p, g_cnt);  cnt0 = (int*)p;   cnt1 = cnt0 + MAXN; }
    { void* p; cudaGetSymbolAddress(&p, g_off);  off0 = (int*)p;   off1 = off0 + (MAXN + 1); }
    { void* p; cudaGetSymbolAddress(&p, g_bsum); bs0  = (int*)p;   bs1  = bs0 + 64; }
    { void* p; cudaGetSymbolAddress(&p, g_psrc); ps0  = (int*)p;   ps1  = ps0 + MAXE; }
    { void* p; cudaGetSymbolAddress(&p, g_pw);   pw0  = (float*)p; pw1  = pw0 + MAXE; }

    float* out    = (float*)d_out;
    float* aggr_a = out;
    float* aggr_b = out + (size_t)NA * D128;

    const size_t smem_bytes = SMEM_FLOATS * sizeof(float);
    cudaFuncSetAttribute(gemm_tc<0>, cudaFuncAttributeMaxDynamicSharedMemorySize, (int)smem_bytes);
    cudaFuncSetAttribute(gemm_tc<1>, cudaFuncAttributeMaxDynamicSharedMemorySize, (int)smem_bytes);
    cudaFuncSetAttribute(gemm_tc<2>, cudaFuncAttributeMaxDynamicSharedMemorySize, (int)smem_bytes);

    const int blkA  = (NA + BM - 1) / BM;
    const int blkB  = (NB + BM - 1) / BM;
    const int eblkA = (E_ab + 255) / 256;
    const int eblkB = (E_ba + 255) / 256;
    const int nbB   = (NB + 1023) / 1024;   // scan blocks, dir0 (dst in b)
    const int nbA   = (NA + 1023) / 1024;   // dir1 (dst in a)

    // --- CSR preprocessing ---
    cudaMemsetAsync(cnt0, 0, sizeof(int) * MAXN * 2, 0);
    hist_kernel<<<eblkA, 256>>>(ei_ab + E_ab, E_ab, cnt0);
    hist_kernel<<<eblkB, 256>>>(ei_ba + E_ba, E_ba, cnt1);
    scan1_kernel<<<nbB, 1024>>>(cnt0, off0, bs0, NB);
    scan1_kernel<<<nbA, 1024>>>(cnt1, off1, bs1, NA);
    scan2_kernel<<<1, 64>>>(bs0, nbB);
    scan2_kernel<<<1, 64>>>(bs1, nbA);
    scan3_kernel<<<nbB, 1024>>>(off0, bs0, NB, E_ab);
    scan3_kernel<<<nbA, 1024>>>(off1, bs1, NA, E_ba);
    cudaMemsetAsync(cnt0, 0, sizeof(int) * MAXN * 2, 0);
    fill_kernel<<<eblkA, 256>>>(ei_ab, ei_ab + E_ab, ea_ab, E_ab, off0, cnt0, ps0, pw0);
    fill_kernel<<<eblkB, 256>>>(ei_ba, ei_ba + E_ba, ea_ba, E_ba, off1, cnt1, ps1, pw1);

    // --- a -> b ---
    gemm_tc<0><<<blkA, 256, smem_bytes>>>(x_a, w1_ab, b1_ab, nullptr, nullptr, H, NA);
    gemm_tc<1><<<blkA, 256, smem_bytes>>>(H,   w2_ab, b2_ab, nullptr, nullptr, T, NA);
    gather_kernel<<<(NB + 7) / 8, 256>>>(T, x_b, off0, ps0, pw0, aggr_b, NB);

    // --- b -> a ---
    gemm_tc<0><<<blkB, 256, smem_bytes>>>(x_b, w1_ba, b1_ba, nullptr, nullptr, H, NB);
    gemm_tc<1><<<blkB, 256, smem_bytes>>>(H,   w2_ba, b2_ba, nullptr, nullptr, T, NB);
    gather_kernel<<<(NA + 7) / 8, 256>>>(T, x_a, off1, ps1, pw1, aggr_a, NA);

    // --- node updates (fused LN, in place on out) ---
    gemm_tc<2><<<blkA, 256, smem_bytes>>>(aggr_a, wu_a, bu_a, g_a, be_a, aggr_a, NA);
    gemm_tc<2><<<blkB, 256, smem_bytes>>>(aggr_b, wu_b, bu_b, g_b, be_b, aggr_b, NB);
}

// round 8
// speedup vs baseline: 2.2269x; 1.1814x over previous
#include <cuda_runtime.h>
#include <cstdint>

// ---------------------------------------------------------------------------
// HeteroGraphConv, D=128.
//   CSR preprocess (side stream): hist -> 3-stage scan -> fill (int2 edges)
//   per direction (own stream):
//     T = (relu(x@w1+b1))@w2+b2      (single fused tf32 mma kernel, smem H)
//     aggr[d] = x[d] + sum w_e*T[src_e]   (CSR gather, warp/row)
//     out = relu(LN(aggr@wu+bu)*g+be)     (tf32 GEMM + fused LN, in-place)
// ---------------------------------------------------------------------------

#define D128 128
#define MAXN 50176
#define MAXE 450048

__device__ float g_T0[MAXN * D128];
__device__ float g_T1[MAXN * D128];
__device__ int   g_cnt [2][MAXN];
__device__ int   g_off [2][MAXN + 1];
__device__ int   g_bsum[2][64];
__device__ int2  g_edge[2][MAXE];

__device__ __forceinline__ unsigned f2tf32(float f) {
    unsigned r;
    asm("cvt.rna.tf32.f32 %0, %1;" : "=r"(r) : "f"(f));
    return r;
}
__device__ __forceinline__ float tf32f(float f) { return __uint_as_float(f2tf32(f)); }

// ---------------------------------------------------------------------------
// Fused edge-MLP: T[M,128] = relu(A@W1+b1)@W2+b2, all tiles resident in smem.
// Per block: 128 rows. smem: X[128][132] | Wb[128][132] | Ht[128][132].
// ---------------------------------------------------------------------------
#define TS 132
#define TILE (128 * TS)
#define MLP_SMEM (3 * TILE * sizeof(float))

__global__ __launch_bounds__(256)
void mlp_fused(const float* __restrict__ A,
               const float* __restrict__ W1, const float* __restrict__ b1,
               const float* __restrict__ W2, const float* __restrict__ b2,
               float* __restrict__ T, int M)
{
    extern __shared__ float smem[];
    float* X  = smem;
    float* Wb = smem + TILE;
    float* Ht = smem + 2 * TILE;

    const int tid  = threadIdx.x;
    const int lane = tid & 31;
    const int wid  = tid >> 5;
    const int wm   = wid >> 1;
    const int wn   = wid & 1;
    const int g    = lane >> 2;
    const int t    = lane & 3;
    const int row0 = blockIdx.x * 128;

    // Load X tile (bounds-checked) + W1, converting to tf32.
    #pragma unroll
    for (int i = 0; i < 16; i++) {
        int idx = tid + i * 256, r = idx >> 5, c = (idx & 31) * 4;
        int gr = row0 + r;
        float4 v = (gr < M) ? *reinterpret_cast<const float4*>(A + (size_t)gr * D128 + c)
                            : make_float4(0.f, 0.f, 0.f, 0.f);
        float4 w = *reinterpret_cast<const float4*>(W1 + (size_t)r * D128 + c);
        float4 vt = make_float4(tf32f(v.x), tf32f(v.y), tf32f(v.z), tf32f(v.w));
        float4 wt = make_float4(tf32f(w.x), tf32f(w.y), tf32f(w.z), tf32f(w.w));
        *reinterpret_cast<float4*>(X  + r * TS + c) = vt;
        *reinterpret_cast<float4*>(Wb + r * TS + c) = wt;
    }
    __syncthreads();

    float acc[2][8][4];
    #pragma unroll
    for (int mf = 0; mf < 2; mf++)
        #pragma unroll
        for (int nf = 0; nf < 8; nf++)
            #pragma unroll
            for (int j = 0; j < 4; j++) acc[mf][nf][j] = 0.0f;

    auto mainloop = [&](const float* Am, const float* Bm) {
        #pragma unroll
        for (int ks = 0; ks < 16; ks++) {
            const int k0 = ks * 8;
            unsigned a[2][4];
            #pragma unroll
            for (int mf = 0; mf < 2; mf++) {
                const float* ap = Am + (wm * 32 + mf * 16 + g) * TS + k0 + t;
                a[mf][0] = __float_as_uint(ap[0]);
                a[mf][1] = __float_as_uint(ap[8 * TS]);
                a[mf][2] = __float_as_uint(ap[4]);
                a[mf][3] = __float_as_uint(ap[8 * TS + 4]);
            }
            unsigned b[8][2];
            #pragma unroll
            for (int nf = 0; nf < 8; nf++) {
                const float* wp = Bm + (k0 + t) * TS + wn * 64 + nf * 8 + g;
                b[nf][0] = __float_as_uint(wp[0]);
                b[nf][1] = __float_as_uint(wp[4 * TS]);
            }
            #pragma unroll
            for (int mf = 0; mf < 2; mf++)
                #pragma unroll
                for (int nf = 0; nf < 8; nf++)
                    asm volatile(
                        "mma.sync.aligned.m16n8k8.row.col.f32.tf32.tf32.f32 "
                        "{%0,%1,%2,%3}, {%4,%5,%6,%7}, {%8,%9}, {%0,%1,%2,%3};"
                        : "+f"(acc[mf][nf][0]), "+f"(acc[mf][nf][1]),
                          "+f"(acc[mf][nf][2]), "+f"(acc[mf][nf][3])
                        : "r"(a[mf][0]), "r"(a[mf][1]), "r"(a[mf][2]), "r"(a[mf][3]),
                          "r"(b[nf][0]), "r"(b[nf][1]));
        }
    };

    // Phase 1: H = relu(X@W1 + b1) -> Ht (tf32)
    mainloop(X, Wb);
    #pragma unroll
    for (int mf = 0; mf < 2; mf++) {
        int r_ = wm * 32 + mf * 16 + g;
        #pragma unroll
        for (int nf = 0; nf < 8; nf++) {
            int col = wn * 64 + nf * 8 + 2 * t;
            float b0 = b1[col], b1v = b1[col + 1];
            Ht[r_ * TS + col]           = tf32f(fmaxf(acc[mf][nf][0] + b0,  0.f));
            Ht[r_ * TS + col + 1]       = tf32f(fmaxf(acc[mf][nf][1] + b1v, 0.f));
            Ht[(r_ + 8) * TS + col]     = tf32f(fmaxf(acc[mf][nf][2] + b0,  0.f));
            Ht[(r_ + 8) * TS + col + 1] = tf32f(fmaxf(acc[mf][nf][3] + b1v, 0.f));
            acc[mf][nf][0] = acc[mf][nf][1] = acc[mf][nf][2] = acc[mf][nf][3] = 0.f;
        }
    }
    __syncthreads();

    // Swap W2 into Wb.
    #pragma unroll
    for (int i = 0; i < 16; i++) {
        int idx = tid + i * 256, r = idx >> 5, c = (idx & 31) * 4;
        float4 w = *reinterpret_cast<const float4*>(W2 + (size_t)r * D128 + c);
        float4 wt = make_float4(tf32f(w.x), tf32f(w.y), tf32f(w.z), tf32f(w.w));
        *reinterpret_cast<float4*>(Wb + r * TS + c) = wt;
    }
    __syncthreads();

    // Phase 2: T = Ht@W2 + b2
    mainloop(Ht, Wb);
    #pragma unroll
    for (int mf = 0; mf < 2; mf++) {
        int r_ = row0 + wm * 32 + mf * 16 + g;
        #pragma unroll
        for (int nf = 0; nf < 8; nf++) {
            int col = wn * 64 + nf * 8 + 2 * t;
            float b0 = b2[col], b1v = b2[col + 1];
            float2 v0, v1;
            v0.x = acc[mf][nf][0] + b0; v0.y = acc[mf][nf][1] + b1v;
            v1.x = acc[mf][nf][2] + b0; v1.y = acc[mf][nf][3] + b1v;
            if (r_ < M)
                *reinterpret_cast<float2*>(T + (size_t)r_ * D128 + col) = v0;
            if (r_ + 8 < M)
                *reinterpret_cast<float2*>(T + (size_t)(r_ + 8) * D128 + col) = v1;
        }
    }
}

// ---------------------------------------------------------------------------
// Node-update GEMM with fused bias + LayerNorm + ReLU (in-place safe).
// Double-buffered k-chunks.
// ---------------------------------------------------------------------------
#define BKC 32
#define AS_STRIDE 36
#define WS_STRIDE 132
#define AS_SIZE (128 * AS_STRIDE)
#define WS_SIZE (BKC * WS_STRIDE)
#define BUF_SIZE (AS_SIZE + WS_SIZE)
#define LN_SMEM (2 * BUF_SIZE * sizeof(float))

__global__ __launch_bounds__(256)
void gemm_ln(const float* __restrict__ A,
             const float* __restrict__ W,
             const float* __restrict__ bias,
             const float* __restrict__ gamma,
             const float* __restrict__ beta,
             float* __restrict__ C,
             int M)
{
    extern __shared__ float smem[];

    const int tid  = threadIdx.x;
    const int lane = tid & 31;
    const int wid  = tid >> 5;
    const int wm   = wid >> 1;
    const int wn   = wid & 1;
    const int g    = lane >> 2;
    const int t    = lane & 3;
    const int row0 = blockIdx.x * 128;

    float acc[2][8][4];
    #pragma unroll
    for (int mf = 0; mf < 2; mf++)
        #pragma unroll
        for (int nf = 0; nf < 8; nf++)
            #pragma unroll
            for (int j = 0; j < 4; j++) acc[mf][nf][j] = 0.0f;

    float4 aLd[4], wLd[4];

    auto ldg_chunk = [&](int kc) {
        #pragma unroll
        for (int i = 0; i < 4; i++) {
            int idx = tid + i * 256;
            int r = idx >> 3, c = (idx & 7) * 4;
            int gr = row0 + r;
            aLd[i] = (gr < M)
                ? *reinterpret_cast<const float4*>(A + (size_t)gr * D128 + kc + c)
                : make_float4(0.f, 0.f, 0.f, 0.f);
        }
        #pragma unroll
        for (int i = 0; i < 4; i++) {
            int idx = tid + i * 256;
            int r = idx >> 5, c = (idx & 31) * 4;
            wLd[i] = *reinterpret_cast<const float4*>(W + (size_t)(kc + r) * D128 + c);
        }
    };
    auto sts_chunk = [&](int b) {
        float* as = smem + b * BUF_SIZE;
        float* ws = as + AS_SIZE;
        #pragma unroll
        for (int i = 0; i < 4; i++) {
            int idx = tid + i * 256;
            int r = idx >> 3, c = (idx & 7) * 4;
            float4 o = make_float4(tf32f(aLd[i].x), tf32f(aLd[i].y),
                                   tf32f(aLd[i].z), tf32f(aLd[i].w));
            *reinterpret_cast<float4*>(as + r * AS_STRIDE + c) = o;
        }
        #pragma unroll
        for (int i = 0; i < 4; i++) {
            int idx = tid + i * 256;
            int r = idx >> 5, c = (idx & 31) * 4;
            float4 o = make_float4(tf32f(wLd[i].x), tf32f(wLd[i].y),
                                   tf32f(wLd[i].z), tf32f(wLd[i].w));
            *reinterpret_cast<float4*>(ws + r * WS_STRIDE + c) = o;
        }
    };

    ldg_chunk(0);
    sts_chunk(0);
    __syncthreads();

    #pragma unroll
    for (int c = 0; c < 4; c++) {
        if (c < 3) ldg_chunk((c + 1) * BKC);
        const float* as = smem + (c & 1) * BUF_SIZE;
        const float* ws = as + AS_SIZE;
        #pragma unroll
        for (int ks = 0; ks < 4; ks++) {
            const int k0 = ks * 8;
            unsigned a[2][4];
            #pragma unroll
            for (int mf = 0; mf < 2; mf++) {
                const float* ap = as + (wm * 32 + mf * 16 + g) * AS_STRIDE + k0 + t;
                a[mf][0] = __float_as_uint(ap[0]);
                a[mf][1] = __float_as_uint(ap[8 * AS_STRIDE]);
                a[mf][2] = __float_as_uint(ap[4]);
                a[mf][3] = __float_as_uint(ap[8 * AS_STRIDE + 4]);
            }
            unsigned b[8][2];
            #pragma unroll
            for (int nf = 0; nf < 8; nf++) {
                const float* wp = ws + (k0 + t) * WS_STRIDE + wn * 64 + nf * 8 + g;
                b[nf][0] = __float_as_uint(wp[0]);
                b[nf][1] = __float_as_uint(wp[4 * WS_STRIDE]);
            }
            #pragma unroll
            for (int mf = 0; mf < 2; mf++)
                #pragma unroll
                for (int nf = 0; nf < 8; nf++)
                    asm volatile(
                        "mma.sync.aligned.m16n8k8.row.col.f32.tf32.tf32.f32 "
                        "{%0,%1,%2,%3}, {%4,%5,%6,%7}, {%8,%9}, {%0,%1,%2,%3};"
                        : "+f"(acc[mf][nf][0]), "+f"(acc[mf][nf][1]),
                          "+f"(acc[mf][nf][2]), "+f"(acc[mf][nf][3])
                        : "r"(a[mf][0]), "r"(a[mf][1]), "r"(a[mf][2]), "r"(a[mf][3]),
                          "r"(b[nf][0]), "r"(b[nf][1]));
        }
        __syncthreads();
        if (c < 3) {
            sts_chunk((c + 1) & 1);
            __syncthreads();
        }
    }

    // LN epilogue via smem transpose
    float* S = smem;   // [128][132]
    #pragma unroll
    for (int mf = 0; mf < 2; mf++) {
        int r_ = wm * 32 + mf * 16 + g;
        #pragma unroll
        for (int nf = 0; nf < 8; nf++) {
            int col = wn * 64 + nf * 8 + 2 * t;
            S[r_ * 132 + col]           = acc[mf][nf][0];
            S[r_ * 132 + col + 1]       = acc[mf][nf][1];
            S[(r_ + 8) * 132 + col]     = acc[mf][nf][2];
            S[(r_ + 8) * 132 + col + 1] = acc[mf][nf][3];
        }
    }
    __syncthreads();

    float4 bv = *reinterpret_cast<const float4*>(bias  + lane * 4);
    float4 gv = *reinterpret_cast<const float4*>(gamma + lane * 4);
    float4 ev = *reinterpret_cast<const float4*>(beta  + lane * 4);

    #pragma unroll
    for (int rr = 0; rr < 16; rr++) {
        int r_ = wid * 16 + rr;
        float4 h = *reinterpret_cast<const float4*>(S + r_ * 132 + lane * 4);
        h.x += bv.x; h.y += bv.y; h.z += bv.z; h.w += bv.w;
        float s = h.x + h.y + h.z + h.w;
        #pragma unroll
        for (int o = 16; o > 0; o >>= 1) s += __shfl_xor_sync(0xFFFFFFFFu, s, o);
        float mu = s * (1.0f / 128.0f);
        float d0 = h.x - mu, d1 = h.y - mu, d2 = h.z - mu, d3 = h.w - mu;
        float q = d0 * d0 + d1 * d1 + d2 * d2 + d3 * d3;
        #pragma unroll
        for (int o = 16; o > 0; o >>= 1) q += __shfl_xor_sync(0xFFFFFFFFu, q, o);
        float rstd = rsqrtf(q * (1.0f / 128.0f) + 1e-5f);
        int grow = row0 + r_;
        if (grow < M) {
            float4 o4;
            o4.x = fmaxf(d0 * rstd * gv.x + ev.x, 0.f);
            o4.y = fmaxf(d1 * rstd * gv.y + ev.y, 0.f);
            o4.z = fmaxf(d2 * rstd * gv.z + ev.z, 0.f);
            o4.w = fmaxf(d3 * rstd * gv.w + ev.w, 0.f);
            *reinterpret_cast<float4*>(C + (size_t)grow * D128 + lane * 4) = o4;
        }
    }
}

// ---------------------------------------------------------------------------
// CSR construction
// ---------------------------------------------------------------------------
__global__ void hist_kernel(const int* __restrict__ dst, int E, int* __restrict__ cnt)
{
    int e = blockIdx.x * blockDim.x + threadIdx.x;
    if (e < E) atomicAdd(&cnt[dst[e]], 1);
}

__global__ __launch_bounds__(1024)
void scan1_kernel(const int* __restrict__ cnt, int* __restrict__ off,
                  int* __restrict__ bsum, int n)
{
    __shared__ int ws[32];
    const int tid = threadIdx.x, lane = tid & 31, wid = tid >> 5;
    int i = blockIdx.x * 1024 + tid;
    int v = (i < n) ? cnt[i] : 0;
    int x = v;
    #pragma unroll
    for (int o = 1; o < 32; o <<= 1) {
        int y = __shfl_up_sync(0xFFFFFFFFu, x, o);
        if (lane >= o) x += y;
    }
    if (lane == 31) ws[wid] = x;
    __syncthreads();
    if (wid == 0) {
        int w = ws[lane];
        #pragma unroll
        for (int o = 1; o < 32; o <<= 1) {
            int y = __shfl_up_sync(0xFFFFFFFFu, w, o);
            if (lane >= o) w += y;
        }
        ws[lane] = w;
    }
    __syncthreads();
    int excl = ((wid == 0) ? 0 : ws[wid - 1]) + x - v;
    if (i < n) off[i] = excl;
    if (tid == 0) bsum[blockIdx.x] = ws[31];
}

__global__ void scan2_kernel(int* __restrict__ bsum, int nb)
{
    __shared__ int s[64];
    int l = threadIdx.x;
    s[l] = (l < nb) ? bsum[l] : 0;
    __syncthreads();
    #pragma unroll
    for (int o = 1; o < 64; o <<= 1) {
        int t = (l >= o) ? s[l - o] : 0;
        __syncthreads();
        s[l] += t;
        __syncthreads();
    }
    if (l < nb) bsum[l] = (l > 0) ? s[l - 1] : 0;
}

__global__ void scan3_kernel(int* __restrict__ off, const int* __restrict__ bsum,
                             int n, int E)
{
    int i = blockIdx.x * blockDim.x + threadIdx.x;
    if (i < n) off[i] += bsum[i >> 10];
    if (i == 0) off[n] = E;
}

__global__ void fill_kernel(const int* __restrict__ src, const int* __restrict__ dst,
                            const float* __restrict__ ea, int E,
                            const int* __restrict__ off, int* __restrict__ cur,
                            int2* __restrict__ edge)
{
    int e = blockIdx.x * blockDim.x + threadIdx.x;
    if (e >= E) return;
    int d = dst[e];
    int pos = off[d] + atomicAdd(&cur[d], 1);
    edge[pos] = make_int2(src[e], __float_as_int(ea[e]));
}

// ---------------------------------------------------------------------------
// Gather: one warp per dst row; residual folded in via init from x.
// ---------------------------------------------------------------------------
__global__ __launch_bounds__(256)
void gather_kernel(const float* __restrict__ T,
                   const float* __restrict__ x,
                   const int* __restrict__ off,
                   const int2* __restrict__ edge,
                   float* __restrict__ aggr,
                   int N)
{
    int w    = (blockIdx.x * blockDim.x + threadIdx.x) >> 5;
    int lane = threadIdx.x & 31;
    if (w >= N) return;

    float4 acc = reinterpret_cast<const float4*>(x + (size_t)w * D128)[lane];

    int j  = __ldg(off + w);
    int s1 = __ldg(off + w + 1);

    for (; j + 1 < s1; j += 2) {
        int2 eA = __ldg(edge + j), eB = __ldg(edge + j + 1);
        float wA = __int_as_float(eA.y), wB = __int_as_float(eB.y);
        float4 vA = reinterpret_cast<const float4*>(T + (size_t)eA.x * D128)[lane];
        float4 vB = reinterpret_cast<const float4*>(T + (size_t)eB.x * D128)[lane];
        acc.x = fmaf(wA, vA.x, acc.x); acc.x = fmaf(wB, vB.x, acc.x);
        acc.y = fmaf(wA, vA.y, acc.y); acc.y = fmaf(wB, vB.y, acc.y);
        acc.z = fmaf(wA, vA.z, acc.z); acc.z = fmaf(wB, vB.z, acc.z);
        acc.w = fmaf(wA, vA.w, acc.w); acc.w = fmaf(wB, vB.w, acc.w);
    }
    if (j < s1) {
        int2 eA = __ldg(edge + j);
        float wA = __int_as_float(eA.y);
        float4 vA = reinterpret_cast<const float4*>(T + (size_t)eA.x * D128)[lane];
        acc.x = fmaf(wA, vA.x, acc.x);
        acc.y = fmaf(wA, vA.y, acc.y);
        acc.z = fmaf(wA, vA.z, acc.z);
        acc.w = fmaf(wA, vA.w, acc.w);
    }

    reinterpret_cast<float4*>(aggr + (size_t)w * D128)[lane] = acc;
}

extern "C" void kernel_launch(void* const* d_in, const int* in_sizes, int n_in,
                              void* d_out, int out_size)
{
    const float* x_a   = (const float*)d_in[0];
    const float* x_b   = (const float*)d_in[1];
    const int*   ei_ab = (const int*)  d_in[2];
    const float* ea_ab = (const float*)d_in[3];
    const int*   ei_ba = (const int*)  d_in[4];
    const float* ea_ba = (const float*)d_in[5];
    const float* w1_ab = (const float*)d_in[6];
    const float* b1_ab = (const float*)d_in[7];
    const float* w2_ab = (const float*)d_in[8];
    const float* b2_ab = (const float*)d_in[9];
    const float* w1_ba = (const float*)d_in[10];
    const float* b1_ba = (const float*)d_in[11];
    const float* w2_ba = (const float*)d_in[12];
    const float* b2_ba = (const float*)d_in[13];
    const float* wu_a  = (const float*)d_in[14];
    const float* bu_a  = (const float*)d_in[15];
    const float* g_a   = (const float*)d_in[16];
    const float* be_a  = (const float*)d_in[17];
    const float* wu_b  = (const float*)d_in[18];
    const float* bu_b  = (const float*)d_in[19];
    const float* g_b   = (const float*)d_in[20];
    const float* be_b  = (const float*)d_in[21];

    const int NA   = in_sizes[0] / D128;
    const int NB   = in_sizes[1] / D128;
    const int E_ab = in_sizes[3];
    const int E_ba = in_sizes[5];

    float *T0, *T1;
    int *cnt0, *cnt1, *off0, *off1, *bs0, *bs1;
    int2 *ed0, *ed1;
    cudaGetSymbolAddress((void**)&T0, g_T0);
    cudaGetSymbolAddress((void**)&T1, g_T1);
    { void* p; cudaGetSymbolAddress(&p, g_cnt);  cnt0 = (int*)p;  cnt1 = cnt0 + MAXN; }
    { void* p; cudaGetSymbolAddress(&p, g_off);  off0 = (int*)p;  off1 = off0 + (MAXN + 1); }
    { void* p; cudaGetSymbolAddress(&p, g_bsum); bs0  = (int*)p;  bs1  = bs0 + 64; }
    { void* p; cudaGetSymbolAddress(&p, g_edge); ed0  = (int2*)p; ed1  = ed0 + MAXE; }

    float* out    = (float*)d_out;
    float* aggr_a = out;
    float* aggr_b = out + (size_t)NA * D128;

    // Lazy one-time setup of streams/events and smem attributes (first call
    // happens BEFORE graph capture — the correctness run — so no API calls
    // occur during capture).
    static cudaStream_t s1 = nullptr, s2 = nullptr, s3 = nullptr;
    static cudaEvent_t evRoot, evPre, evA, evB;
    if (!s1) {
        cudaStreamCreateWithFlags(&s1, cudaStreamNonBlocking);
        cudaStreamCreateWithFlags(&s2, cudaStreamNonBlocking);
        cudaStreamCreateWithFlags(&s3, cudaStreamNonBlocking);
        cudaEventCreateWithFlags(&evRoot, cudaEventDisableTiming);
        cudaEventCreateWithFlags(&evPre,  cudaEventDisableTiming);
        cudaEventCreateWithFlags(&evA,    cudaEventDisableTiming);
        cudaEventCreateWithFlags(&evB,    cudaEventDisableTiming);
        cudaFuncSetAttribute(mlp_fused, cudaFuncAttributeMaxDynamicSharedMemorySize, (int)MLP_SMEM);
        cudaFuncSetAttribute(gemm_ln,   cudaFuncAttributeMaxDynamicSharedMemorySize, (int)LN_SMEM);
    }

    const int blkA  = (NA + 127) / 128;
    const int blkB  = (NB + 127) / 128;
    const int eblkA = (E_ab + 255) / 256;
    const int eblkB = (E_ba + 255) / 256;
    const int nbB   = (NB + 1023) / 1024;
    const int nbA   = (NA + 1023) / 1024;

    // Fork from capture stream (0).
    cudaEventRecord(evRoot, 0);
    cudaStreamWaitEvent(s1, evRoot, 0);
    cudaStreamWaitEvent(s2, evRoot, 0);
    cudaStreamWaitEvent(s3, evRoot, 0);

    // --- s1: CSR preprocessing (both directions) ---
    cudaMemsetAsync(cnt0, 0, sizeof(int) * MAXN * 2, s1);
    hist_kernel<<<eblkA, 256, 0, s1>>>(ei_ab + E_ab, E_ab, cnt0);
    hist_kernel<<<eblkB, 256, 0, s1>>>(ei_ba + E_ba, E_ba, cnt1);
    scan1_kernel<<<nbB, 1024, 0, s1>>>(cnt0, off0, bs0, NB);
    scan1_kernel<<<nbA, 1024, 0, s1>>>(cnt1, off1, bs1, NA);
    scan2_kernel<<<1, 64, 0, s1>>>(bs0, nbB);
    scan2_kernel<<<1, 64, 0, s1>>>(bs1, nbA);
    scan3_kernel<<<nbB, 1024, 0, s1>>>(off0, bs0, NB, E_ab);
    scan3_kernel<<<nbA, 1024, 0, s1>>>(off1, bs1, NA, E_ba);
    cudaMemsetAsync(cnt0, 0, sizeof(int) * MAXN * 2, s1);
    fill_kernel<<<eblkA, 256, 0, s1>>>(ei_ab, ei_ab + E_ab, ea_ab, E_ab, off0, cnt0, ed0);
    fill_kernel<<<eblkB, 256, 0, s1>>>(ei_ba, ei_ba + E_ba, ea_ba, E_ba, off1, cnt1, ed1);
    cudaEventRecord(evPre, s1);

    // --- s2: a->b chain -> out_b ---
    mlp_fused<<<blkA, 256, MLP_SMEM, s2>>>(x_a, w1_ab, b1_ab, w2_ab, b2_ab, T0, NA);
    cudaStreamWaitEvent(s2, evPre, 0);
    gather_kernel<<<(NB + 7) / 8, 256, 0, s2>>>(T0, x_b, off0, ed0, aggr_b, NB);
    gemm_ln<<<blkB, 256, LN_SMEM, s2>>>(aggr_b, wu_b, bu_b, g_b, be_b, aggr_b, NB);
    cudaEventRecord(evB, s2);

    // --- s3: b->a chain -> out_a ---
    mlp_fused<<<blkB, 256, MLP_SMEM, s3>>>(x_b, w1_ba, b1_ba, w2_ba, b2_ba, T1, NB);
    cudaStreamWaitEvent(s3, evPre, 0);
    gather_kernel<<<(NA + 7) / 8, 256, 0, s3>>>(T1, x_a, off1, ed1, aggr_a, NA);
    gemm_ln<<<blkA, 256, LN_SMEM, s3>>>(aggr_a, wu_a, bu_a, g_a, be_a, aggr_a, NA);
    cudaEventRecord(evA, s3);

    // Join back to capture stream.
    cudaStreamWaitEvent(0, evA, 0);
    cudaStreamWaitEvent(0, evB, 0);
}

// round 9
// speedup vs baseline: 2.2548x; 1.0125x over previous
#include <cuda_runtime.h>
#include <cstdint>

// ---------------------------------------------------------------------------
// HeteroGraphConv, D=128.
//   CSR preprocess (side stream): hist -> 3-stage scan -> fill (int2 edges)
//   per direction (own stream):
//     T = (relu(x@w1+b1))@w2+b2      (single fused tf32 mma kernel, smem H)
//     aggr[d] = x[d] + sum w_e*T[src_e]   (CSR gather, warp/row)
//     out = relu(LN(aggr@wu+bu)*g+be)     (tf32 GEMM + fused LN, in-place)
//   This round: 512-thread / 16-warp MMA kernels (4x4 warp grid, 32x32/warp)
// ---------------------------------------------------------------------------

#define D128 128
#define MAXN 50176
#define MAXE 450048

__device__ float g_T0[MAXN * D128];
__device__ float g_T1[MAXN * D128];
__device__ int   g_cnt [2][MAXN];
__device__ int   g_off [2][MAXN + 1];
__device__ int   g_bsum[2][64];
__device__ int2  g_edge[2][MAXE];

__device__ __forceinline__ unsigned f2tf32(float f) {
    unsigned r;
    asm("cvt.rna.tf32.f32 %0, %1;" : "=r"(r) : "f"(f));
    return r;
}
__device__ __forceinline__ float tf32f(float f) { return __uint_as_float(f2tf32(f)); }

// ---------------------------------------------------------------------------
// Fused edge-MLP: T[M,128] = relu(A@W1+b1)@W2+b2, tiles resident in smem.
// 512 threads, 16 warps: warp (wm, wn) owns rows wm*32..+31, cols wn*32..+31.
// smem: X[128][132] | Wb[128][132] | Ht[128][132].
// ---------------------------------------------------------------------------
#define TS 132
#define TILE (128 * TS)
#define MLP_SMEM (3 * TILE * sizeof(float))

__global__ __launch_bounds__(512)
void mlp_fused(const float* __restrict__ A,
               const float* __restrict__ W1, const float* __restrict__ b1,
               const float* __restrict__ W2, const float* __restrict__ b2,
               float* __restrict__ T, int M)
{
    extern __shared__ float smem[];
    float* X  = smem;
    float* Wb = smem + TILE;
    float* Ht = smem + 2 * TILE;

    const int tid  = threadIdx.x;
    const int lane = tid & 31;
    const int wid  = tid >> 5;
    const int wm   = wid >> 2;          // 0..3 : rows wm*32
    const int wn   = wid & 3;           // 0..3 : cols wn*32
    const int g    = lane >> 2;         // 0..7
    const int t    = lane & 3;          // 0..3
    const int row0 = blockIdx.x * 128;

    // Load X tile (bounds-checked) + W1, converting to tf32.
    #pragma unroll
    for (int i = 0; i < 8; i++) {
        int idx = tid + i * 512, r = idx >> 5, c = (idx & 31) * 4;
        int gr = row0 + r;
        float4 v = (gr < M) ? *reinterpret_cast<const float4*>(A + (size_t)gr * D128 + c)
                            : make_float4(0.f, 0.f, 0.f, 0.f);
        float4 w = *reinterpret_cast<const float4*>(W1 + (size_t)r * D128 + c);
        float4 vt = make_float4(tf32f(v.x), tf32f(v.y), tf32f(v.z), tf32f(v.w));
        float4 wt = make_float4(tf32f(w.x), tf32f(w.y), tf32f(w.z), tf32f(w.w));
        *reinterpret_cast<float4*>(X  + r * TS + c) = vt;
        *reinterpret_cast<float4*>(Wb + r * TS + c) = wt;
    }
    __syncthreads();

    float acc[2][4][4];
    #pragma unroll
    for (int mf = 0; mf < 2; mf++)
        #pragma unroll
        for (int nf = 0; nf < 4; nf++)
            #pragma unroll
            for (int j = 0; j < 4; j++) acc[mf][nf][j] = 0.0f;

    auto mainloop = [&](const float* Am, const float* Bm) {
        #pragma unroll
        for (int ks = 0; ks < 16; ks++) {
            const int k0 = ks * 8;
            unsigned a[2][4];
            #pragma unroll
            for (int mf = 0; mf < 2; mf++) {
                const float* ap = Am + (wm * 32 + mf * 16 + g) * TS + k0 + t;
                a[mf][0] = __float_as_uint(ap[0]);
                a[mf][1] = __float_as_uint(ap[8 * TS]);
                a[mf][2] = __float_as_uint(ap[4]);
                a[mf][3] = __float_as_uint(ap[8 * TS + 4]);
            }
            unsigned b[4][2];
            #pragma unroll
            for (int nf = 0; nf < 4; nf++) {
                const float* wp = Bm + (k0 + t) * TS + wn * 32 + nf * 8 + g;
                b[nf][0] = __float_as_uint(wp[0]);
                b[nf][1] = __float_as_uint(wp[4 * TS]);
            }
            #pragma unroll
            for (int mf = 0; mf < 2; mf++)
                #pragma unroll
                for (int nf = 0; nf < 4; nf++)
                    asm volatile(
                        "mma.sync.aligned.m16n8k8.row.col.f32.tf32.tf32.f32 "
                        "{%0,%1,%2,%3}, {%4,%5,%6,%7}, {%8,%9}, {%0,%1,%2,%3};"
                        : "+f"(acc[mf][nf][0]), "+f"(acc[mf][nf][1]),
                          "+f"(acc[mf][nf][2]), "+f"(acc[mf][nf][3])
                        : "r"(a[mf][0]), "r"(a[mf][1]), "r"(a[mf][2]), "r"(a[mf][3]),
                          "r"(b[nf][0]), "r"(b[nf][1]));
        }
    };

    // Phase 1: H = relu(X@W1 + b1) -> Ht (tf32)
    mainloop(X, Wb);
    #pragma unroll
    for (int mf = 0; mf < 2; mf++) {
        int r_ = wm * 32 + mf * 16 + g;
        #pragma unroll
        for (int nf = 0; nf < 4; nf++) {
            int col = wn * 32 + nf * 8 + 2 * t;
            float b0 = b1[col], b1v = b1[col + 1];
            Ht[r_ * TS + col]           = tf32f(fmaxf(acc[mf][nf][0] + b0,  0.f));
            Ht[r_ * TS + col + 1]       = tf32f(fmaxf(acc[mf][nf][1] + b1v, 0.f));
            Ht[(r_ + 8) * TS + col]     = tf32f(fmaxf(acc[mf][nf][2] + b0,  0.f));
            Ht[(r_ + 8) * TS + col + 1] = tf32f(fmaxf(acc[mf][nf][3] + b1v, 0.f));
            acc[mf][nf][0] = acc[mf][nf][1] = acc[mf][nf][2] = acc[mf][nf][3] = 0.f;
        }
    }
    __syncthreads();

    // Swap W2 into Wb.
    #pragma unroll
    for (int i = 0; i < 8; i++) {
        int idx = tid + i * 512, r = idx >> 5, c = (idx & 31) * 4;
        float4 w = *reinterpret_cast<const float4*>(W2 + (size_t)r * D128 + c);
        float4 wt = make_float4(tf32f(w.x), tf32f(w.y), tf32f(w.z), tf32f(w.w));
        *reinterpret_cast<float4*>(Wb + r * TS + c) = wt;
    }
    __syncthreads();

    // Phase 2: T = Ht@W2 + b2
    mainloop(Ht, Wb);
    #pragma unroll
    for (int mf = 0; mf < 2; mf++) {
        int r_ = row0 + wm * 32 + mf * 16 + g;
        #pragma unroll
        for (int nf = 0; nf < 4; nf++) {
            int col = wn * 32 + nf * 8 + 2 * t;
            float b0 = b2[col], b1v = b2[col + 1];
            float2 v0, v1;
            v0.x = acc[mf][nf][0] + b0; v0.y = acc[mf][nf][1] + b1v;
            v1.x = acc[mf][nf][2] + b0; v1.y = acc[mf][nf][3] + b1v;
            if (r_ < M)
                *reinterpret_cast<float2*>(T + (size_t)r_ * D128 + col) = v0;
            if (r_ + 8 < M)
                *reinterpret_cast<float2*>(T + (size_t)(r_ + 8) * D128 + col) = v1;
        }
    }
}

// ---------------------------------------------------------------------------
// Node-update GEMM with fused bias + LayerNorm + ReLU (in-place safe).
// 512 threads, 16 warps (32x32 per warp), double-buffered k-chunks.
// ---------------------------------------------------------------------------
#define BKC 32
#define AS_STRIDE 36
#define WS_STRIDE 132
#define AS_SIZE (128 * AS_STRIDE)
#define WS_SIZE (BKC * WS_STRIDE)
#define BUF_SIZE (AS_SIZE + WS_SIZE)
#define LN_SMEM (2 * BUF_SIZE * sizeof(float))

__global__ __launch_bounds__(512)
void gemm_ln(const float* __restrict__ A,
             const float* __restrict__ W,
             const float* __restrict__ bias,
             const float* __restrict__ gamma,
             const float* __restrict__ beta,
             float* __restrict__ C,
             int M)
{
    extern __shared__ float smem[];

    const int tid  = threadIdx.x;
    const int lane = tid & 31;
    const int wid  = tid >> 5;
    const int wm   = wid >> 2;
    const int wn   = wid & 3;
    const int g    = lane >> 2;
    const int t    = lane & 3;
    const int row0 = blockIdx.x * 128;

    float acc[2][4][4];
    #pragma unroll
    for (int mf = 0; mf < 2; mf++)
        #pragma unroll
        for (int nf = 0; nf < 4; nf++)
            #pragma unroll
            for (int j = 0; j < 4; j++) acc[mf][nf][j] = 0.0f;

    float4 aLd[2], wLd[2];

    auto ldg_chunk = [&](int kc) {
        #pragma unroll
        for (int i = 0; i < 2; i++) {
            int idx = tid + i * 512;
            int r = idx >> 3, c = (idx & 7) * 4;
            int gr = row0 + r;
            aLd[i] = (gr < M)
                ? *reinterpret_cast<const float4*>(A + (size_t)gr * D128 + kc + c)
                : make_float4(0.f, 0.f, 0.f, 0.f);
        }
        #pragma unroll
        for (int i = 0; i < 2; i++) {
            int idx = tid + i * 512;
            int r = idx >> 5, c = (idx & 31) * 4;
            wLd[i] = *reinterpret_cast<const float4*>(W + (size_t)(kc + r) * D128 + c);
        }
    };
    auto sts_chunk = [&](int b) {
        float* as = smem + b * BUF_SIZE;
        float* ws = as + AS_SIZE;
        #pragma unroll
        for (int i = 0; i < 2; i++) {
            int idx = tid + i * 512;
            int r = idx >> 3, c = (idx & 7) * 4;
            float4 o = make_float4(tf32f(aLd[i].x), tf32f(aLd[i].y),
                                   tf32f(aLd[i].z), tf32f(aLd[i].w));
            *reinterpret_cast<float4*>(as + r * AS_STRIDE + c) = o;
        }
        #pragma unroll
        for (int i = 0; i < 2; i++) {
            int idx = tid + i * 512;
            int r = idx >> 5, c = (idx & 31) * 4;
            float4 o = make_float4(tf32f(wLd[i].x), tf32f(wLd[i].y),
                                   tf32f(wLd[i].z), tf32f(wLd[i].w));
            *reinterpret_cast<float4*>(ws + r * WS_STRIDE + c) = o;
        }
    };

    ldg_chunk(0);
    sts_chunk(0);
    __syncthreads();

    #pragma unroll
    for (int c = 0; c < 4; c++) {
        if (c < 3) ldg_chunk((c + 1) * BKC);
        const float* as = smem + (c & 1) * BUF_SIZE;
        const float* ws = as + AS_SIZE;
        #pragma unroll
        for (int ks = 0; ks < 4; ks++) {
            const int k0 = ks * 8;
            unsigned a[2][4];
            #pragma unroll
            for (int mf = 0; mf < 2; mf++) {
                const float* ap = as + (wm * 32 + mf * 16 + g) * AS_STRIDE + k0 + t;
                a[mf][0] = __float_as_uint(ap[0]);
                a[mf][1] = __float_as_uint(ap[8 * AS_STRIDE]);
                a[mf][2] = __float_as_uint(ap[4]);
                a[mf][3] = __float_as_uint(ap[8 * AS_STRIDE + 4]);
            }
            unsigned b[4][2];
            #pragma unroll
            for (int nf = 0; nf < 4; nf++) {
                const float* wp = ws + (k0 + t) * WS_STRIDE + wn * 32 + nf * 8 + g;
                b[nf][0] = __float_as_uint(wp[0]);
                b[nf][1] = __float_as_uint(wp[4 * WS_STRIDE]);
            }
            #pragma unroll
            for (int mf = 0; mf < 2; mf++)
                #pragma unroll
                for (int nf = 0; nf < 4; nf++)
                    asm volatile(
                        "mma.sync.aligned.m16n8k8.row.col.f32.tf32.tf32.f32 "
                        "{%0,%1,%2,%3}, {%4,%5,%6,%7}, {%8,%9}, {%0,%1,%2,%3};"
                        : "+f"(acc[mf][nf][0]), "+f"(acc[mf][nf][1]),
                          "+f"(acc[mf][nf][2]), "+f"(acc[mf][nf][3])
                        : "r"(a[mf][0]), "r"(a[mf][1]), "r"(a[mf][2]), "r"(a[mf][3]),
                          "r"(b[nf][0]), "r"(b[nf][1]));
        }
        __syncthreads();
        if (c < 3) {
            sts_chunk((c + 1) & 1);
            __syncthreads();
        }
    }

    // LN epilogue via smem transpose
    float* S = smem;   // [128][132]
    #pragma unroll
    for (int mf = 0; mf < 2; mf++) {
        int r_ = wm * 32 + mf * 16 + g;
        #pragma unroll
        for (int nf = 0; nf < 4; nf++) {
            int col = wn * 32 + nf * 8 + 2 * t;
            S[r_ * 132 + col]           = acc[mf][nf][0];
            S[r_ * 132 + col + 1]       = acc[mf][nf][1];
            S[(r_ + 8) * 132 + col]     = acc[mf][nf][2];
            S[(r_ + 8) * 132 + col + 1] = acc[mf][nf][3];
        }
    }
    __syncthreads();

    float4 bv = *reinterpret_cast<const float4*>(bias  + lane * 4);
    float4 gv = *reinterpret_cast<const float4*>(gamma + lane * 4);
    float4 ev = *reinterpret_cast<const float4*>(beta  + lane * 4);

    #pragma unroll
    for (int rr = 0; rr < 8; rr++) {
        int r_ = wid * 8 + rr;
        float4 h = *reinterpret_cast<const float4*>(S + r_ * 132 + lane * 4);
        h.x += bv.x; h.y += bv.y; h.z += bv.z; h.w += bv.w;
        float s = h.x + h.y + h.z + h.w;
        #pragma unroll
        for (int o = 16; o > 0; o >>= 1) s += __shfl_xor_sync(0xFFFFFFFFu, s, o);
        float mu = s * (1.0f / 128.0f);
        float d0 = h.x - mu, d1 = h.y - mu, d2 = h.z - mu, d3 = h.w - mu;
        float q = d0 * d0 + d1 * d1 + d2 * d2 + d3 * d3;
        #pragma unroll
        for (int o = 16; o > 0; o >>= 1) q += __shfl_xor_sync(0xFFFFFFFFu, q, o);
        float rstd = rsqrtf(q * (1.0f / 128.0f) + 1e-5f);
        int grow = row0 + r_;
        if (grow < M) {
            float4 o4;
            o4.x = fmaxf(d0 * rstd * gv.x + ev.x, 0.f);
            o4.y = fmaxf(d1 * rstd * gv.y + ev.y, 0.f);
            o4.z = fmaxf(d2 * rstd * gv.z + ev.z, 0.f);
            o4.w = fmaxf(d3 * rstd * gv.w + ev.w, 0.f);
            *reinterpret_cast<float4*>(C + (size_t)grow * D128 + lane * 4) = o4;
        }
    }
}

// ---------------------------------------------------------------------------
// CSR construction
// ---------------------------------------------------------------------------
__global__ void hist_kernel(const int* __restrict__ dst, int E, int* __restrict__ cnt)
{
    int e = blockIdx.x * blockDim.x + threadIdx.x;
    if (e < E) atomicAdd(&cnt[dst[e]], 1);
}

__global__ __launch_bounds__(1024)
void scan1_kernel(const int* __restrict__ cnt, int* __restrict__ off,
                  int* __restrict__ bsum, int n)
{
    __shared__ int ws[32];
    const int tid = threadIdx.x, lane = tid & 31, wid = tid >> 5;
    int i = blockIdx.x * 1024 + tid;
    int v = (i < n) ? cnt[i] : 0;
    int x = v;
    #pragma unroll
    for (int o = 1; o < 32; o <<= 1) {
        int y = __shfl_up_sync(0xFFFFFFFFu, x, o);
        if (lane >= o) x += y;
    }
    if (lane == 31) ws[wid] = x;
    __syncthreads();
    if (wid == 0) {
        int w = ws[lane];
        #pragma unroll
        for (int o = 1; o < 32; o <<= 1) {
            int y = __shfl_up_sync(0xFFFFFFFFu, w, o);
            if (lane >= o) w += y;
        }
        ws[lane] = w;
    }
    __syncthreads();
    int excl = ((wid == 0) ? 0 : ws[wid - 1]) + x - v;
    if (i < n) off[i] = excl;
    if (tid == 0) bsum[blockIdx.x] = ws[31];
}

__global__ void scan2_kernel(int* __restrict__ bsum, int nb)
{
    __shared__ int s[64];
    int l = threadIdx.x;
    s[l] = (l < nb) ? bsum[l] : 0;
    __syncthreads();
    #pragma unroll
    for (int o = 1; o < 64; o <<= 1) {
        int t = (l >= o) ? s[l - o] : 0;
        __syncthreads();
        s[l] += t;
        __syncthreads();
    }
    if (l < nb) bsum[l] = (l > 0) ? s[l - 1] : 0;
}

__global__ void scan3_kernel(int* __restrict__ off, const int* __restrict__ bsum,
                             int n, int E)
{
    int i = blockIdx.x * blockDim.x + threadIdx.x;
    if (i < n) off[i] += bsum[i >> 10];
    if (i == 0) off[n] = E;
}

__global__ void fill_kernel(const int* __restrict__ src, const int* __restrict__ dst,
                            const float* __restrict__ ea, int E,
                            const int* __restrict__ off, int* __restrict__ cur,
                            int2* __restrict__ edge)
{
    int e = blockIdx.x * blockDim.x + threadIdx.x;
    if (e >= E) return;
    int d = dst[e];
    int pos = off[d] + atomicAdd(&cur[d], 1);
    edge[pos] = make_int2(src[e], __float_as_int(ea[e]));
}

// ---------------------------------------------------------------------------
// Gather: one warp per dst row; residual folded in via init from x.
// ---------------------------------------------------------------------------
__global__ __launch_bounds__(256)
void gather_kernel(const float* __restrict__ T,
                   const float* __restrict__ x,
                   const int* __restrict__ off,
                   const int2* __restrict__ edge,
                   float* __restrict__ aggr,
                   int N)
{
    int w    = (blockIdx.x * blockDim.x + threadIdx.x) >> 5;
    int lane = threadIdx.x & 31;
    if (w >= N) return;

    float4 acc = reinterpret_cast<const float4*>(x + (size_t)w * D128)[lane];

    int j  = __ldg(off + w);
    int s1 = __ldg(off + w + 1);

    for (; j + 1 < s1; j += 2) {
        int2 eA = __ldg(edge + j), eB = __ldg(edge + j + 1);
        float wA = __int_as_float(eA.y), wB = __int_as_float(eB.y);
        float4 vA = reinterpret_cast<const float4*>(T + (size_t)eA.x * D128)[lane];
        float4 vB = reinterpret_cast<const float4*>(T + (size_t)eB.x * D128)[lane];
        acc.x = fmaf(wA, vA.x, acc.x); acc.x = fmaf(wB, vB.x, acc.x);
        acc.y = fmaf(wA, vA.y, acc.y); acc.y = fmaf(wB, vB.y, acc.y);
        acc.z = fmaf(wA, vA.z, acc.z); acc.z = fmaf(wB, vB.z, acc.z);
        acc.w = fmaf(wA, vA.w, acc.w); acc.w = fmaf(wB, vB.w, acc.w);
    }
    if (j < s1) {
        int2 eA = __ldg(edge + j);
        float wA = __int_as_float(eA.y);
        float4 vA = reinterpret_cast<const float4*>(T + (size_t)eA.x * D128)[lane];
        acc.x = fmaf(wA, vA.x, acc.x);
        acc.y = fmaf(wA, vA.y, acc.y);
        acc.z = fmaf(wA, vA.z, acc.z);
        acc.w = fmaf(wA, vA.w, acc.w);
    }

    reinterpret_cast<float4*>(aggr + (size_t)w * D128)[lane] = acc;
}

extern "C" void kernel_launch(void* const* d_in, const int* in_sizes, int n_in,
                              void* d_out, int out_size)
{
    const float* x_a   = (const float*)d_in[0];
    const float* x_b   = (const float*)d_in[1];
    const int*   ei_ab = (const int*)  d_in[2];
    const float* ea_ab = (const float*)d_in[3];
    const int*   ei_ba = (const int*)  d_in[4];
    const float* ea_ba = (const float*)d_in[5];
    const float* w1_ab = (const float*)d_in[6];
    const float* b1_ab = (const float*)d_in[7];
    const float* w2_ab = (const float*)d_in[8];
    const float* b2_ab = (const float*)d_in[9];
    const float* w1_ba = (const float*)d_in[10];
    const float* b1_ba = (const float*)d_in[11];
    const float* w2_ba = (const float*)d_in[12];
    const float* b2_ba = (const float*)d_in[13];
    const float* wu_a  = (const float*)d_in[14];
    const float* bu_a  = (const float*)d_in[15];
    const float* g_a   = (const float*)d_in[16];
    const float* be_a  = (const float*)d_in[17];
    const float* wu_b  = (const float*)d_in[18];
    const float* bu_b  = (const float*)d_in[19];
    const float* g_b   = (const float*)d_in[20];
    const float* be_b  = (const float*)d_in[21];

    const int NA   = in_sizes[0] / D128;
    const int NB   = in_sizes[1] / D128;
    const int E_ab = in_sizes[3];
    const int E_ba = in_sizes[5];

    float *T0, *T1;
    int *cnt0, *cnt1, *off0, *off1, *bs0, *bs1;
    int2 *ed0, *ed1;
    cudaGetSymbolAddress((void**)&T0, g_T0);
    cudaGetSymbolAddress((void**)&T1, g_T1);
    { void* p; cudaGetSymbolAddress(&p, g_cnt);  cnt0 = (int*)p;  cnt1 = cnt0 + MAXN; }
    { void* p; cudaGetSymbolAddress(&p, g_off);  off0 = (int*)p;  off1 = off0 + (MAXN + 1); }
    { void* p; cudaGetSymbolAddress(&p, g_bsum); bs0  = (int*)p;  bs1  = bs0 + 64; }
    { void* p; cudaGetSymbolAddress(&p, g_edge); ed0  = (int2*)p; ed1  = ed0 + MAXE; }

    float* out    = (float*)d_out;
    float* aggr_a = out;
    float* aggr_b = out + (size_t)NA * D128;

    // Lazy one-time setup (first call happens BEFORE graph capture).
    static cudaStream_t s1 = nullptr, s2 = nullptr, s3 = nullptr;
    static cudaEvent_t evRoot, evPre, evA, evB;
    if (!s1) {
        cudaStreamCreateWithFlags(&s1, cudaStreamNonBlocking);
        cudaStreamCreateWithFlags(&s2, cudaStreamNonBlocking);
        cudaStreamCreateWithFlags(&s3, cudaStreamNonBlocking);
        cudaEventCreateWithFlags(&evRoot, cudaEventDisableTiming);
        cudaEventCreateWithFlags(&evPre,  cudaEventDisableTiming);
        cudaEventCreateWithFlags(&evA,    cudaEventDisableTiming);
        cudaEventCreateWithFlags(&evB,    cudaEventDisableTiming);
        cudaFuncSetAttribute(mlp_fused, cudaFuncAttributeMaxDynamicSharedMemorySize, (int)MLP_SMEM);
        cudaFuncSetAttribute(gemm_ln,   cudaFuncAttributeMaxDynamicSharedMemorySize, (int)LN_SMEM);
    }

    const int blkA  = (NA + 127) / 128;
    const int blkB  = (NB + 127) / 128;
    const int eblkA = (E_ab + 255) / 256;
    const int eblkB = (E_ba + 255) / 256;
    const int nbB   = (NB + 1023) / 1024;
    const int nbA   = (NA + 1023) / 1024;

    // Fork from capture stream (0).
    cudaEventRecord(evRoot, 0);
    cudaStreamWaitEvent(s1, evRoot, 0);
    cudaStreamWaitEvent(s2, evRoot, 0);
    cudaStreamWaitEvent(s3, evRoot, 0);

    // --- s1: CSR preprocessing (both directions) ---
    cudaMemsetAsync(cnt0, 0, sizeof(int) * MAXN * 2, s1);
    hist_kernel<<<eblkA, 256, 0, s1>>>(ei_ab + E_ab, E_ab, cnt0);
    hist_kernel<<<eblkB, 256, 0, s1>>>(ei_ba + E_ba, E_ba, cnt1);
    scan1_kernel<<<nbB, 1024, 0, s1>>>(cnt0, off0, bs0, NB);
    scan1_kernel<<<nbA, 1024, 0, s1>>>(cnt1, off1, bs1, NA);
    scan2_kernel<<<1, 64, 0, s1>>>(bs0, nbB);
    scan2_kernel<<<1, 64, 0, s1>>>(bs1, nbA);
    scan3_kernel<<<nbB, 1024, 0, s1>>>(off0, bs0, NB, E_ab);
    scan3_kernel<<<nbA, 1024, 0, s1>>>(off1, bs1, NA, E_ba);
    cudaMemsetAsync(cnt0, 0, sizeof(int) * MAXN * 2, s1);
    fill_kernel<<<eblkA, 256, 0, s1>>>(ei_ab, ei_ab + E_ab, ea_ab, E_ab, off0, cnt0, ed0);
    fill_kernel<<<eblkB, 256, 0, s1>>>(ei_ba, ei_ba + E_ba, ea_ba, E_ba, off1, cnt1, ed1);
    cudaEventRecord(evPre, s1);

    // --- s2: a->b chain -> out_b ---
    mlp_fused<<<blkA, 512, MLP_SMEM, s2>>>(x_a, w1_ab, b1_ab, w2_ab, b2_ab, T0, NA);
    cudaStreamWaitEvent(s2, evPre, 0);
    gather_kernel<<<(NB + 7) / 8, 256, 0, s2>>>(T0, x_b, off0, ed0, aggr_b, NB);
    gemm_ln<<<blkB, 512, LN_SMEM, s2>>>(aggr_b, wu_b, bu_b, g_b, be_b, aggr_b, NB);
    cudaEventRecord(evB, s2);

    // --- s3: b->a chain -> out_a ---
    mlp_fused<<<blkB, 512, MLP_SMEM, s3>>>(x_b, w1_ba, b1_ba, w2_ba, b2_ba, T1, NB);
    cudaStreamWaitEvent(s3, evPre, 0);
    gather_kernel<<<(NA + 7) / 8, 256, 0, s3>>>(T1, x_a, off1, ed1, aggr_a, NA);
    gemm_ln<<<blkA, 512, LN_SMEM, s3>>>(aggr_a, wu_a, bu_a, g_a, be_a, aggr_a, NA);
    cudaEventRecord(evA, s3);

    // Join back to capture stream.
    cudaStreamWaitEvent(0, evA, 0);
    cudaStreamWaitEvent(0, evB, 0);
}